// round 10
// baseline (speedup 1.0000x reference)
#include <cuda_runtime.h>
#include <math.h>

#define NN 8192
#define CC 512
#define KK 64
#define NBLK (NN/64)        // 128 row-blocks of 64 (gemm + flags)
#define PHI_ROWS 128
#define PHI_NBLK (NN/PHI_ROWS)   // 64 blocks per matrix
#define CH 32                    // c per chunk
#define CHUNKS (CC/CH)           // 16
#define FILL_BLKS 896

// Scratch (device globals — no allocation allowed)
__device__ float g_phi_i[NN*KK];
__device__ float g_phi_j[NN*KK];
__device__ float g_Wab[CC*KK*2]; // [c][k][{A,B}]: A=1/s^2, B=-2m/s^2 (tf32-rounded)
__device__ float g_t3[KK];       // sum_c m^2/s^2
__device__ int   g_nz[2][NBLK];  // per-64-row-block nonzero flags

__device__ __forceinline__ unsigned tf32_of(float f) {
    unsigned r; asm("cvt.rna.tf32.f32 %0, %1;" : "=r"(r) : "f"(f)); return r;
}

#define MMA_TF32(d0,d1,d2,d3,a0,a1,a2,a3,b0,b1)                              \
    asm("mma.sync.aligned.m16n8k8.row.col.f32.tf32.tf32.f32 "                \
        "{%0,%1,%2,%3}, {%4,%5,%6,%7}, {%8,%9}, {%0,%1,%2,%3};"              \
        : "+f"(d0), "+f"(d1), "+f"(d2), "+f"(d3)                             \
        : "r"(a0), "r"(a1), "r"(a2), "r"(a3), "r"(b0), "r"(b1))

#define CP16(dst_s32, src)                                                   \
    asm volatile("cp.async.cg.shared.global [%0], [%1], 16;"                 \
                 :: "r"(dst_s32), "l"(src))
#define CP_COMMIT() asm volatile("cp.async.commit_group;")
#define CP_WAIT1()  asm volatile("cp.async.wait_group 1;")
#define CP_WAIT0()  asm volatile("cp.async.wait_group 0;")

// ---------------------------------------------------------------------------
// Prep: W[c][k][{A,B}] (tf32-rounded), t3[k] = sum_c m^2/s^2 (exact fp32)
// ---------------------------------------------------------------------------
__global__ __launch_bounds__(512)
void prep_kernel(const float* __restrict__ means,
                 const float* __restrict__ scales) {
    const int k = blockIdx.x;
    const int t = threadIdx.x;          // = c
    float s   = scales[k*CC + t];
    float m   = means [k*CC + t];
    float is2 = 1.0f / (s * s);
    float A = is2;
    float B = -2.0f * m * is2;
    g_Wab[((size_t)t*KK + k)*2 + 0] = __uint_as_float(tf32_of(A));
    g_Wab[((size_t)t*KK + k)*2 + 1] = __uint_as_float(tf32_of(B));
    float v = m * m * is2;
    #pragma unroll
    for (int o = 16; o > 0; o >>= 1)
        v += __shfl_down_sync(0xffffffffu, v, o);
    __shared__ float red[16];
    if ((t & 31) == 0) red[t >> 5] = v;
    __syncthreads();
    if (t < 16) {
        float x = red[t];
        #pragma unroll
        for (int o = 8; o > 0; o >>= 1)
            x += __shfl_down_sync(0xffffu, x, o);
        if (t == 0) g_t3[k] = x;
    }
}

// ---------------------------------------------------------------------------
// Fused phi (tensor-core, double-buffered cp.async — R9-proven inner loop)
// + zero-fill of the 256MB output in trailing store-only blocks.
// Phi blocks [0, 2*PHI_NBLK) run first; fill blocks overlap on DRAM writes.
// ---------------------------------------------------------------------------
__global__ __launch_bounds__(256)
void phi_fill_kernel(const float* __restrict__ f_i,
                     const float* __restrict__ f_j,
                     const float* __restrict__ weights,
                     float* __restrict__ out) {
    const int bid = blockIdx.x;
    const int t   = threadIdx.x;

    if (bid >= 2*PHI_NBLK) {
        // ---- fill role: zero the whole output ----
        const float4 z = make_float4(0.f, 0.f, 0.f, 0.f);
        float4* o4 = (float4*)out;
        const size_t total4 = (size_t)NN * NN / 4;   // 16M float4
        size_t idx = (size_t)(bid - 2*PHI_NBLK) * 256 + t;
        const size_t stride = (size_t)FILL_BLKS * 256;
        #pragma unroll 4
        for (size_t p = idx; p < total4; p += stride)
            o4[p] = z;
        return;
    }

    // ---- phi role (R9 inner loop, unchanged) ----
    const int isI = (bid < PHI_NBLK);
    const float* __restrict__ f = isI ? f_i : f_j;
    float* __restrict__ phi = isI ? g_phi_i : g_phi_j;
    const int blk = isI ? bid : (bid - PHI_NBLK);
    const int n0 = blk * PHI_ROWS;

    __shared__ float fS[2][PHI_ROWS * 36];   // [buf][row][c] rows padded to 36
    __shared__ float wS[2][CH * 132];        // [buf][c][k*2 interleaved] pad 132

    const int w    = t >> 5;
    const int lane = t & 31;
    const int g    = lane >> 2;           // 0..7
    const int tid  = lane & 3;            // 0..3

    const int rt0 = (w & 3) * 2;          // row-tile indices rt0, rt0+1
    const int nb  = (w >> 2) * 32;        // n(k) base for this warp's 4 n-tiles

    // per-thread load indices (4 f + 4 w chunks of 16B each)
    int frow[4], fc4[4], wrow[4], wq[4];
    #pragma unroll
    for (int v = 0; v < 4; v++) {
        int vid = t + v * 256;
        frow[v] = vid >> 3;               // 8 x16B per f row
        fc4[v]  = (vid & 7) * 4;
        wrow[v] = vid >> 5;               // 32 x16B per w row
        wq[v]   = (vid & 31) * 4;
    }

    float acc[2][4][4];                   // [rt][nt][4]
    #pragma unroll
    for (int a = 0; a < 2; a++)
        #pragma unroll
        for (int b = 0; b < 4; b++)
            #pragma unroll
            for (int c = 0; c < 4; c++) acc[a][b][c] = 0.f;

    // prologue: issue chunk 0 into buf 0
    {
        const unsigned fD = (unsigned)__cvta_generic_to_shared(&fS[0][0]);
        const unsigned wD = (unsigned)__cvta_generic_to_shared(&wS[0][0]);
        #pragma unroll
        for (int v = 0; v < 4; v++) {
            CP16(fD + (frow[v] * 36 + fc4[v]) * 4,
                 f + (size_t)(n0 + frow[v]) * CC + fc4[v]);
            CP16(wD + (wrow[v] * 132 + wq[v]) * 4,
                 g_Wab + ((size_t)wrow[v] * KK) * 2 + wq[v]);
        }
        CP_COMMIT();
    }

    for (int ch = 0; ch < CHUNKS; ch++) {
        const int buf = ch & 1;
        if (ch + 1 < CHUNKS) {
            const int cc = (ch + 1) * CH;
            const int nb2 = buf ^ 1;
            const unsigned fD = (unsigned)__cvta_generic_to_shared(&fS[nb2][0]);
            const unsigned wD = (unsigned)__cvta_generic_to_shared(&wS[nb2][0]);
            #pragma unroll
            for (int v = 0; v < 4; v++) {
                CP16(fD + (frow[v] * 36 + fc4[v]) * 4,
                     f + (size_t)(n0 + frow[v]) * CC + cc + fc4[v]);
                CP16(wD + (wrow[v] * 132 + wq[v]) * 4,
                     g_Wab + ((size_t)(cc + wrow[v]) * KK) * 2 + wq[v]);
            }
            CP_COMMIT();
            CP_WAIT1();   // chunk ch complete; ch+1 still streaming
        } else {
            CP_WAIT0();
        }
        __syncthreads();

        #pragma unroll
        for (int kc = 0; kc < CH / 8; kc++) {
            // a-fragments for 2 row-tiles: load f, build f and f^2 frags
            unsigned af[2][4], af2[2][4];
            #pragma unroll
            for (int rt = 0; rt < 2; rt++) {
                const int R = (rt0 + rt) * 16;
                #pragma unroll
                for (int q = 0; q < 4; q++) {
                    int row = R + g + (q & 1) * 8;
                    int col = kc * 8 + tid + (q >> 1) * 4;
                    float fv = fS[buf][row * 36 + col];
                    af [rt][q] = tf32_of(fv);
                    af2[rt][q] = tf32_of(fv * fv);
                }
            }
            #pragma unroll
            for (int nt = 0; nt < 4; nt++) {
                // b-fragments: one LDS.64 yields (A,B) at (c,k)
                int kcol = nb + nt * 8 + g;
                float2 w0 = *(const float2*)&wS[buf][(kc * 8 + tid)     * 132 + kcol * 2];
                float2 w1 = *(const float2*)&wS[buf][(kc * 8 + tid + 4) * 132 + kcol * 2];
                unsigned bA0 = __float_as_uint(w0.x), bB0 = __float_as_uint(w0.y);
                unsigned bA1 = __float_as_uint(w1.x), bB1 = __float_as_uint(w1.y);
                #pragma unroll
                for (int rt = 0; rt < 2; rt++) {
                    MMA_TF32(acc[rt][nt][0], acc[rt][nt][1], acc[rt][nt][2], acc[rt][nt][3],
                             af2[rt][0], af2[rt][1], af2[rt][2], af2[rt][3], bA0, bA1);
                    MMA_TF32(acc[rt][nt][0], acc[rt][nt][1], acc[rt][nt][2], acc[rt][nt][3],
                             af [rt][0], af [rt][1], af [rt][2], af [rt][3], bB0, bB1);
                }
            }
        }
        __syncthreads();   // buf free for reuse by chunk ch+2's issue
    }

    // epilogue: d = -(acc + t3);  phi = exp(d) (* w for i-side)
    int lnz = 0;
    #pragma unroll
    for (int nt = 0; nt < 4; nt++) {
        const int col0 = nb + nt * 8 + 2 * tid;
        const float nt30 = -g_t3[col0];
        const float nt31 = -g_t3[col0 + 1];
        const float w0 = isI ? weights[col0]     : 1.0f;
        const float w1 = isI ? weights[col0 + 1] : 1.0f;
        #pragma unroll
        for (int rt = 0; rt < 2; rt++) {
            const int Rg = n0 + (rt0 + rt) * 16 + g;
            float p0 = expf(nt30 - acc[rt][nt][0]) * w0;
            float p1 = expf(nt31 - acc[rt][nt][1]) * w1;
            float p2 = expf(nt30 - acc[rt][nt][2]) * w0;
            float p3 = expf(nt31 - acc[rt][nt][3]) * w1;
            lnz |= (p0 != 0.f) | (p1 != 0.f) | (p2 != 0.f) | (p3 != 0.f);
            *(float2*)(phi + (size_t)Rg       * KK + col0) = make_float2(p0, p1);
            *(float2*)(phi + (size_t)(Rg + 8) * KK + col0) = make_float2(p2, p3);
        }
    }
    int any = __syncthreads_or(lnz);
    if (t == 0) {
        g_nz[isI ? 0 : 1][2*blk]     = any;
        g_nz[isI ? 0 : 1][2*blk + 1] = any;
    }
}

// ---------------------------------------------------------------------------
// GEMM: zero tiles were already zeroed by the fused fill -> exit immediately.
// Nonzero tiles: 64x64, 256 threads, 4x4 micro-tile (proven path).
// ---------------------------------------------------------------------------
__global__ __launch_bounds__(256)
void gemm_kernel(float* __restrict__ out) {
    const int bm = blockIdx.y;
    const int bn = blockIdx.x;

    if (g_nz[0][bm] == 0 || g_nz[1][bn] == 0) return;

    const int t  = threadIdx.x;
    const int txm = (t & 15) * 4;
    const int tyn = (t >> 4) * 4;

    __shared__ float As[64][68];
    __shared__ float Bs[64][68];
    #pragma unroll
    for (int v = 0; v < 4; v++) {
        int vid = t + v * 256;
        int row = vid >> 4;
        int k4  = (vid & 15) * 4;
        float4 a = *(const float4*)(g_phi_i + (size_t)(bm * 64 + row) * KK + k4);
        As[k4+0][row] = a.x; As[k4+1][row] = a.y; As[k4+2][row] = a.z; As[k4+3][row] = a.w;
        float4 b = *(const float4*)(g_phi_j + (size_t)(bn * 64 + row) * KK + k4);
        Bs[k4+0][row] = b.x; Bs[k4+1][row] = b.y; Bs[k4+2][row] = b.z; Bs[k4+3][row] = b.w;
    }
    __syncthreads();

    float acc[4][4];
    #pragma unroll
    for (int i = 0; i < 4; i++)
        #pragma unroll
        for (int j = 0; j < 4; j++) acc[i][j] = 0.f;

    #pragma unroll 8
    for (int k = 0; k < 64; k++) {
        float4 a4 = *(const float4*)&As[k][tyn];
        float4 b4 = *(const float4*)&Bs[k][txm];
        float av[4] = {a4.x, a4.y, a4.z, a4.w};
        float bv[4] = {b4.x, b4.y, b4.z, b4.w};
        #pragma unroll
        for (int i = 0; i < 4; i++)
            #pragma unroll
            for (int j = 0; j < 4; j++)
                acc[i][j] = fmaf(av[i], bv[j], acc[i][j]);
    }

    #pragma unroll
    for (int i = 0; i < 4; i++) {
        size_t row = (size_t)(bm * 64 + tyn + i);
        *(float4*)(out + row * NN + bn * 64 + txm) =
            make_float4(acc[i][0], acc[i][1], acc[i][2], acc[i][3]);
    }
}

// ---------------------------------------------------------------------------
extern "C" void kernel_launch(void* const* d_in, const int* in_sizes, int n_in,
                              void* d_out, int out_size) {
    const float* f_i     = (const float*)d_in[0];
    const float* f_j     = (const float*)d_in[1];
    const float* means   = (const float*)d_in[2];
    const float* scales  = (const float*)d_in[3];
    const float* weights = (const float*)d_in[4];
    float* out = (float*)d_out;

    prep_kernel<<<KK, 512>>>(means, scales);
    phi_fill_kernel<<<2*PHI_NBLK + FILL_BLKS, 256>>>(f_i, f_j, weights, out);
    gemm_kernel<<<dim3(NBLK, NBLK), 256>>>(out);
}

// round 11
// speedup vs baseline: 1.1314x; 1.1314x over previous
#include <cuda_runtime.h>
#include <math.h>

#define NN 8192
#define CC 512
#define KK 64
#define NBLK (NN/64)        // 128 row-blocks of 64 (gemm + flags)
#define PHI_ROWS 128
#define PHI_NBLK (NN/PHI_ROWS)   // 64 blocks per matrix
#define CH 32                    // c per chunk
#define CHUNKS (CC/CH)           // 16

// Scratch (device globals — no allocation allowed)
__device__ float g_phi_i[NN*KK];
__device__ float g_phi_j[NN*KK];
__device__ float g_Wab[CC*KK*2]; // [c][k][{A,B}]: A=1/s^2, B=-2m/s^2 (tf32-rounded)
__device__ float g_t3p[4][KK];   // partial sums of m^2/s^2 (4 c-quarters)
__device__ int   g_nz[2][NBLK];  // per-64-row-block nonzero flags

__device__ __forceinline__ unsigned tf32_of(float f) {
    unsigned r; asm("cvt.rna.tf32.f32 %0, %1;" : "=r"(r) : "f"(f)); return r;
}

#define MMA_TF32(d0,d1,d2,d3,a0,a1,a2,a3,b0,b1)                              \
    asm("mma.sync.aligned.m16n8k8.row.col.f32.tf32.tf32.f32 "                \
        "{%0,%1,%2,%3}, {%4,%5,%6,%7}, {%8,%9}, {%0,%1,%2,%3};"              \
        : "+f"(d0), "+f"(d1), "+f"(d2), "+f"(d3)                             \
        : "r"(a0), "r"(a1), "r"(a2), "r"(a3), "r"(b0), "r"(b1))

#define CP16(dst_s32, src)                                                   \
    asm volatile("cp.async.cg.shared.global [%0], [%1], 16;"                 \
                 :: "r"(dst_s32), "l"(src))
#define CP_COMMIT() asm volatile("cp.async.commit_group;")
#define CP_WAIT1()  asm volatile("cp.async.wait_group 1;")
#define CP_WAIT0()  asm volatile("cp.async.wait_group 0;")

__device__ __forceinline__ void stcs4(float* p, float4 v) {
    asm volatile("st.global.cs.v4.f32 [%0], {%1,%2,%3,%4};"
                 :: "l"(p), "f"(v.x), "f"(v.y), "f"(v.z), "f"(v.w));
}

// ---------------------------------------------------------------------------
// Prep: W[c][k][{A,B}] (tf32-rounded), t3 partials per c-quarter.
// Grid (KK, 4): block (k, q) handles c in [q*128, q*128+128), 128 threads.
// ---------------------------------------------------------------------------
__global__ __launch_bounds__(128)
void prep_kernel(const float* __restrict__ means,
                 const float* __restrict__ scales) {
    const int k = blockIdx.x;
    const int q = blockIdx.y;
    const int t = threadIdx.x;
    const int c = q * 128 + t;
    float s   = scales[k*CC + c];
    float m   = means [k*CC + c];
    float is2 = 1.0f / (s * s);
    float A = is2;
    float B = -2.0f * m * is2;
    g_Wab[((size_t)c*KK + k)*2 + 0] = __uint_as_float(tf32_of(A));
    g_Wab[((size_t)c*KK + k)*2 + 1] = __uint_as_float(tf32_of(B));
    float v = m * m * is2;
    #pragma unroll
    for (int o = 16; o > 0; o >>= 1)
        v += __shfl_down_sync(0xffffffffu, v, o);
    __shared__ float red[4];
    if ((t & 31) == 0) red[t >> 5] = v;
    __syncthreads();
    if (t == 0)
        g_t3p[q][k] = (red[0] + red[1]) + (red[2] + red[3]);
}

// ---------------------------------------------------------------------------
// Phi via tensor cores (mma.sync m16n8k8 tf32), double-buffered cp.async
// (R9-proven structure). Fragment path uses raw fp32 bits as tf32 (RZ) —
// no cvt instructions — and __expf in the epilogue.
// ---------------------------------------------------------------------------
__global__ __launch_bounds__(256)
void phi_kernel(const float* __restrict__ f_i, const float* __restrict__ f_j,
                const float* __restrict__ weights) {
    const int isI = (blockIdx.y == 0);
    const float* __restrict__ f = isI ? f_i : f_j;
    float* __restrict__ phi = isI ? g_phi_i : g_phi_j;
    const int n0 = blockIdx.x * PHI_ROWS;

    __shared__ float fS[2][PHI_ROWS * 36];   // [buf][row][c] rows padded to 36
    __shared__ float wS[2][CH * 132];        // [buf][c][k*2 interleaved] pad 132

    const int t    = threadIdx.x;
    const int w    = t >> 5;
    const int lane = t & 31;
    const int g    = lane >> 2;           // 0..7
    const int tid  = lane & 3;            // 0..3

    const int rt0 = (w & 3) * 2;          // row-tile indices rt0, rt0+1
    const int nb  = (w >> 2) * 32;        // n(k) base for this warp's 4 n-tiles

    // per-thread load indices (4 f + 4 w chunks of 16B each)
    int frow[4], fc4[4], wrow[4], wq[4];
    #pragma unroll
    for (int v = 0; v < 4; v++) {
        int vid = t + v * 256;
        frow[v] = vid >> 3;               // 8 x16B per f row
        fc4[v]  = (vid & 7) * 4;
        wrow[v] = vid >> 5;               // 32 x16B per w row
        wq[v]   = (vid & 31) * 4;
    }

    float acc[2][4][4];                   // [rt][nt][4]
    #pragma unroll
    for (int a = 0; a < 2; a++)
        #pragma unroll
        for (int b = 0; b < 4; b++)
            #pragma unroll
            for (int c = 0; c < 4; c++) acc[a][b][c] = 0.f;

    // prologue: issue chunk 0 into buf 0
    {
        const unsigned fD = (unsigned)__cvta_generic_to_shared(&fS[0][0]);
        const unsigned wD = (unsigned)__cvta_generic_to_shared(&wS[0][0]);
        #pragma unroll
        for (int v = 0; v < 4; v++) {
            CP16(fD + (frow[v] * 36 + fc4[v]) * 4,
                 f + (size_t)(n0 + frow[v]) * CC + fc4[v]);
            CP16(wD + (wrow[v] * 132 + wq[v]) * 4,
                 g_Wab + ((size_t)wrow[v] * KK) * 2 + wq[v]);
        }
        CP_COMMIT();
    }

    for (int ch = 0; ch < CHUNKS; ch++) {
        const int buf = ch & 1;
        if (ch + 1 < CHUNKS) {
            const int cc = (ch + 1) * CH;
            const int nb2 = buf ^ 1;
            const unsigned fD = (unsigned)__cvta_generic_to_shared(&fS[nb2][0]);
            const unsigned wD = (unsigned)__cvta_generic_to_shared(&wS[nb2][0]);
            #pragma unroll
            for (int v = 0; v < 4; v++) {
                CP16(fD + (frow[v] * 36 + fc4[v]) * 4,
                     f + (size_t)(n0 + frow[v]) * CC + cc + fc4[v]);
                CP16(wD + (wrow[v] * 132 + wq[v]) * 4,
                     g_Wab + ((size_t)(cc + wrow[v]) * KK) * 2 + wq[v]);
            }
            CP_COMMIT();
            CP_WAIT1();   // chunk ch complete; ch+1 still streaming
        } else {
            CP_WAIT0();
        }
        __syncthreads();

        #pragma unroll
        for (int kc = 0; kc < CH / 8; kc++) {
            // a-fragments: raw fp32 bits are valid tf32 (RZ truncation)
            unsigned af[2][4], af2[2][4];
            #pragma unroll
            for (int rt = 0; rt < 2; rt++) {
                const int R = (rt0 + rt) * 16;
                #pragma unroll
                for (int q = 0; q < 4; q++) {
                    int row = R + g + (q & 1) * 8;
                    int col = kc * 8 + tid + (q >> 1) * 4;
                    float fv = fS[buf][row * 36 + col];
                    af [rt][q] = __float_as_uint(fv);
                    af2[rt][q] = __float_as_uint(fv * fv);
                }
            }
            #pragma unroll
            for (int nt = 0; nt < 4; nt++) {
                // b-fragments: one LDS.64 yields (A,B) at (c,k)
                int kcol = nb + nt * 8 + g;
                float2 w0 = *(const float2*)&wS[buf][(kc * 8 + tid)     * 132 + kcol * 2];
                float2 w1 = *(const float2*)&wS[buf][(kc * 8 + tid + 4) * 132 + kcol * 2];
                unsigned bA0 = __float_as_uint(w0.x), bB0 = __float_as_uint(w0.y);
                unsigned bA1 = __float_as_uint(w1.x), bB1 = __float_as_uint(w1.y);
                #pragma unroll
                for (int rt = 0; rt < 2; rt++) {
                    MMA_TF32(acc[rt][nt][0], acc[rt][nt][1], acc[rt][nt][2], acc[rt][nt][3],
                             af2[rt][0], af2[rt][1], af2[rt][2], af2[rt][3], bA0, bA1);
                    MMA_TF32(acc[rt][nt][0], acc[rt][nt][1], acc[rt][nt][2], acc[rt][nt][3],
                             af [rt][0], af [rt][1], af [rt][2], af [rt][3], bB0, bB1);
                }
            }
        }
        __syncthreads();   // buf free for reuse by chunk ch+2's issue
    }

    // epilogue: d = -(acc + t3);  phi = exp(d) (* w for i-side)
    int lnz = 0;
    #pragma unroll
    for (int nt = 0; nt < 4; nt++) {
        const int col0 = nb + nt * 8 + 2 * tid;
        const float t30 = (g_t3p[0][col0] + g_t3p[1][col0])
                        + (g_t3p[2][col0] + g_t3p[3][col0]);
        const float t31 = (g_t3p[0][col0+1] + g_t3p[1][col0+1])
                        + (g_t3p[2][col0+1] + g_t3p[3][col0+1]);
        const float nt30 = -t30;
        const float nt31 = -t31;
        const float w0 = isI ? weights[col0]     : 1.0f;
        const float w1 = isI ? weights[col0 + 1] : 1.0f;
        #pragma unroll
        for (int rt = 0; rt < 2; rt++) {
            const int Rg = n0 + (rt0 + rt) * 16 + g;
            float p0 = __expf(nt30 - acc[rt][nt][0]) * w0;
            float p1 = __expf(nt31 - acc[rt][nt][1]) * w1;
            float p2 = __expf(nt30 - acc[rt][nt][2]) * w0;
            float p3 = __expf(nt31 - acc[rt][nt][3]) * w1;
            lnz |= (p0 != 0.f) | (p1 != 0.f) | (p2 != 0.f) | (p3 != 0.f);
            *(float2*)(phi + (size_t)Rg       * KK + col0) = make_float2(p0, p1);
            *(float2*)(phi + (size_t)(Rg + 8) * KK + col0) = make_float2(p2, p3);
        }
    }
    int any = __syncthreads_or(lnz);
    if (t == 0) {
        g_nz[isI ? 0 : 1][2*blockIdx.x]     = any;
        g_nz[isI ? 0 : 1][2*blockIdx.x + 1] = any;
    }
}

// ---------------------------------------------------------------------------
// GEMM (proven): out[n,m] = sum_k phi_i[n,k]*phi_j[m,k]. 64x64 tiles,
// 256 threads, 4x4 micro-tile. Zero tiles write zeros (exact). Streaming
// stores (.cs): output is write-once, never re-read.
// ---------------------------------------------------------------------------
__global__ __launch_bounds__(256)
void gemm_kernel(float* __restrict__ out) {
    const int bm = blockIdx.y;
    const int bn = blockIdx.x;
    const int t  = threadIdx.x;
    const int txm = (t & 15) * 4;
    const int tyn = (t >> 4) * 4;

    if (g_nz[0][bm] == 0 || g_nz[1][bn] == 0) {
        float4 z = make_float4(0.f, 0.f, 0.f, 0.f);
        #pragma unroll
        for (int i = 0; i < 4; i++) {
            size_t row = (size_t)(bm * 64 + tyn + i);
            stcs4(out + row * NN + bn * 64 + txm, z);
        }
        return;
    }

    __shared__ float As[64][68];
    __shared__ float Bs[64][68];
    #pragma unroll
    for (int v = 0; v < 4; v++) {
        int vid = t + v * 256;
        int row = vid >> 4;
        int k4  = (vid & 15) * 4;
        float4 a = *(const float4*)(g_phi_i + (size_t)(bm * 64 + row) * KK + k4);
        As[k4+0][row] = a.x; As[k4+1][row] = a.y; As[k4+2][row] = a.z; As[k4+3][row] = a.w;
        float4 b = *(const float4*)(g_phi_j + (size_t)(bn * 64 + row) * KK + k4);
        Bs[k4+0][row] = b.x; Bs[k4+1][row] = b.y; Bs[k4+2][row] = b.z; Bs[k4+3][row] = b.w;
    }
    __syncthreads();

    float acc[4][4];
    #pragma unroll
    for (int i = 0; i < 4; i++)
        #pragma unroll
        for (int j = 0; j < 4; j++) acc[i][j] = 0.f;

    #pragma unroll 8
    for (int k = 0; k < 64; k++) {
        float4 a4 = *(const float4*)&As[k][tyn];
        float4 b4 = *(const float4*)&Bs[k][txm];
        float av[4] = {a4.x, a4.y, a4.z, a4.w};
        float bv[4] = {b4.x, b4.y, b4.z, b4.w};
        #pragma unroll
        for (int i = 0; i < 4; i++)
            #pragma unroll
            for (int j = 0; j < 4; j++)
                acc[i][j] = fmaf(av[i], bv[j], acc[i][j]);
    }

    #pragma unroll
    for (int i = 0; i < 4; i++) {
        size_t row = (size_t)(bm * 64 + tyn + i);
        stcs4(out + row * NN + bn * 64 + txm,
              make_float4(acc[i][0], acc[i][1], acc[i][2], acc[i][3]));
    }
}

// ---------------------------------------------------------------------------
extern "C" void kernel_launch(void* const* d_in, const int* in_sizes, int n_in,
                              void* d_out, int out_size) {
    const float* f_i     = (const float*)d_in[0];
    const float* f_j     = (const float*)d_in[1];
    const float* means   = (const float*)d_in[2];
    const float* scales  = (const float*)d_in[3];
    const float* weights = (const float*)d_in[4];
    float* out = (float*)d_out;

    prep_kernel<<<dim3(KK, 4), 128>>>(means, scales);
    phi_kernel<<<dim3(PHI_NBLK, 2), 256>>>(f_i, f_j, weights);
    gemm_kernel<<<dim3(NBLK, NBLK), 256>>>(out);
}